// round 13
// baseline (speedup 1.0000x reference)
#include <cuda_runtime.h>
#include <math.h>

#define SD     16
#define IDIM   64
#define ODIM   64
#define NBATCH 32
#define SEQLEN 8192
#define LCH    32
#define NCH    (SEQLEN/LCH)          /* 256 chunks per batch */
#define NSUP   16
#define NSC    (NCH/NSUP)
#define DTVAL  1.0f
#define FULLMASK 0xffffffffu

__device__ __align__(16) float g_Ad[SD*SD];
__device__ __align__(16) float g_Bd[SD*IDIM];
__device__ __align__(16) float g_Apow[LCH*SD*SD];          // A^{j+1}, j=0..31
__device__ __align__(16) float g_ALpow[17*SD*SD];          // (A^32)^j, j=0..16
__device__ __align__(16) float g_H[NBATCH*SEQLEN*SD];      // local scan values l
__device__ __align__(16) float g_Pfx[NBATCH*NSC*17*SD];
__device__ __align__(16) float g_Hsup[NBATCH*NSC*SD];

// ---------------- K0: discretization + power tables (1 block, 256 thr) ----------------
__global__ void k0_setup(const float* __restrict__ ll, const float* __restrict__ p,
                         const float* __restrict__ q,  const float* __restrict__ B,
                         const float* __restrict__ P) {
    __shared__ float core[SD*SD], tmp[SD*SD], Ac[SD*SD];
    __shared__ float aug[SD][96];
    __shared__ float fvec[SD];
    __shared__ float prow[96];
    int t = threadIdx.x;

    if (t < SD*SD) {
        int i = t >> 4, j = t & 15;
        float v = p[i] * q[j];
        if (i == j) v -= expf(ll[i]);
        core[t] = v;
    }
    __syncthreads();
    if (t < SD*SD) {
        int i = t >> 4, j = t & 15;
        float s = 0.f;
        for (int k = 0; k < SD; k++) s += P[i*SD+k] * core[k*SD+j];
        tmp[t] = s;
    }
    __syncthreads();
    if (t < SD*SD) {
        int i = t >> 4, j = t & 15;
        float s = 0.f;
        for (int k = 0; k < SD; k++) s += tmp[i*SD+k] * P[j*SD+k];
        Ac[t] = s;
    }
    __syncthreads();
    for (int f = t; f < SD*96; f += 256) {
        int r = f / 96, c = f % 96;
        float v;
        if (c < 16)      v = (r == c      ? 1.f : 0.f) - 0.5f*DTVAL*Ac[r*SD+c];
        else if (c < 32) v = (r == (c-16) ? 1.f : 0.f) + 0.5f*DTVAL*Ac[r*SD+(c-16)];
        else             v = DTVAL * B[r*IDIM + (c-32)];
        aug[r][c] = v;
    }
    __syncthreads();
    for (int col = 0; col < SD; col++) {
        if (t < 96) prow[t] = aug[col][t];
        if (t < SD) fvec[t] = aug[t][col];
        __syncthreads();
        float ipv = 1.f / prow[col];
        for (int f = t; f < SD*96; f += 256) {
            int r = f / 96, c = f % 96;
            if (r == col) aug[r][c] = prow[c] * ipv;
            else          aug[r][c] = fmaf(-fvec[r]*ipv, prow[c], aug[r][c]);
        }
        __syncthreads();
    }
    if (t < SD*SD) { int r = t >> 4, c = t & 15; float v = aug[r][16+c]; g_Ad[t] = v; g_Apow[t] = v; }
    for (int f = t; f < SD*IDIM; f += 256) { int r = f / IDIM, c = f % IDIM; g_Bd[f] = aug[r][32+c]; }
    __syncthreads();
    for (int m = 1; m <= LCH/2; m <<= 1) {
        for (int f = t; f < m*256; f += 256) {
            int i = f >> 8, e = f & 255, r = e >> 4, c2 = e & 15;
            const float* L = g_Apow + i*256 + r*16;
            const float* R = g_Apow + (m-1)*256;
            float s = 0.f;
#pragma unroll
            for (int k = 0; k < 16; k++) s = fmaf(L[k], R[k*16 + c2], s);
            g_Apow[(m+i)*256 + e] = s;
        }
        __syncthreads();
    }
    if (t < 256) {
        int r = t >> 4, c = t & 15;
        g_ALpow[t] = (r == c) ? 1.f : 0.f;
        g_ALpow[256 + t] = g_Apow[(LCH-1)*256 + t];
    }
    __syncthreads();
    for (int m = 1; m <= 8; m <<= 1) {
        for (int f = t; f < m*256; f += 256) {
            int i = (f >> 8) + 1, e = f & 255, r = e >> 4, c2 = e & 15;
            const float* L = g_ALpow + i*256 + r*16;
            const float* R = g_ALpow + m*256;
            float s = 0.f;
#pragma unroll
            for (int k = 0; k < 16; k++) s = fmaf(L[k], R[k*16 + c2], s);
            g_ALpow[(m+i)*256 + e] = s;
        }
        __syncthreads();
    }
}

// ---------------- kBxS: u = x @ Bd^T (4x4 f32x2 tile) + in-smem local scan ----------------
#define XSTR 66
#define USTR 20
__global__ void __launch_bounds__(256) kbxs(const float* __restrict__ x) {
    __shared__ __align__(16) float Xs[128*XSTR];
    __shared__ float Bs[16*66];
    __shared__ float As[16*17];
    int tid = threadIdx.x;
    size_t row0 = (size_t)blockIdx.x * 128;

    for (int i = tid; i < SD*IDIM; i += 256) {
        int nn = i >> 6, kk = i & 63;
        Bs[nn*66 + kk] = g_Bd[i];
    }
    if (tid < SD*SD) As[(tid >> 4)*17 + (tid & 15)] = g_Ad[tid];
#pragma unroll
    for (int i = 0; i < 16; i++) {
        int f = tid + 256*i;
        int r = f >> 5, qq = f & 31;
        float2 v = *(const float2*)(x + (row0 + r)*64 + qq*2);
        *(float2*)&Xs[r*XSTR + qq*2] = v;
    }
    __syncthreads();

    unsigned long long acc[4][4];
    int tr = tid >> 2, tc = tid & 3;
    if (tid < 128) {
#pragma unroll
        for (int m = 0; m < 4; m++)
#pragma unroll
            for (int c = 0; c < 4; c++) acc[m][c] = 0ull;
        const float* xa = Xs + (tr*4)*XSTR;
#pragma unroll
        for (int kp = 0; kp < 32; kp++) {
            unsigned long long a2[4], b2[4];
#pragma unroll
            for (int m = 0; m < 4; m++)
                a2[m] = *(const unsigned long long*)(xa + m*XSTR + 2*kp);
#pragma unroll
            for (int c = 0; c < 4; c++)
                b2[c] = *(const unsigned long long*)(Bs + (tc + 4*c)*66 + 2*kp);
#pragma unroll
            for (int m = 0; m < 4; m++)
#pragma unroll
                for (int c = 0; c < 4; c++)
                    asm("fma.rn.f32x2 %0, %1, %2, %0;"
                        : "+l"(acc[m][c]) : "l"(a2[m]), "l"(b2[c]));
        }
    }
    __syncthreads();
    float* Us = Xs;
    if (tid < 128) {
#pragma unroll
        for (int m = 0; m < 4; m++)
#pragma unroll
            for (int c = 0; c < 4; c++) {
                float lo, hi;
                asm("mov.b64 {%0,%1}, %2;" : "=f"(lo), "=f"(hi) : "l"(acc[m][c]));
                Us[(tr*4 + m)*USTR + tc + 4*c] = lo + hi;
            }
    }
    __syncthreads();

    if (tid < 64) {
        int hw = tid >> 4, n = tid & 15;
        float Ar[16];
#pragma unroll
        for (int k = 0; k < 16; k++) Ar[k] = As[n*17 + k];
        float* u = Us + hw*32*USTR + n;
        float h = 0.f;
        float uc = u[0];
#pragma unroll
        for (int i = 0; i < LCH; i++) {
            float un = (i < LCH-1) ? u[(i+1)*USTR] : 0.f;
            float acc0 = uc, acc1 = 0.f, acc2 = 0.f, acc3 = 0.f;
#pragma unroll
            for (int m = 0; m < 16; m += 4) {
                acc0 = fmaf(Ar[m],   __shfl_sync(FULLMASK, h, m,   16), acc0);
                acc1 = fmaf(Ar[m+1], __shfl_sync(FULLMASK, h, m+1, 16), acc1);
                acc2 = fmaf(Ar[m+2], __shfl_sync(FULLMASK, h, m+2, 16), acc2);
                acc3 = fmaf(Ar[m+3], __shfl_sync(FULLMASK, h, m+3, 16), acc3);
            }
            h = (acc0 + acc1) + (acc2 + acc3);
            u[i*USTR] = h;
            uc = un;
        }
    }
    __syncthreads();

#pragma unroll
    for (int i = 0; i < 2; i++) {
        int f = tid + 256*i;
        int r = f >> 2, qq = f & 3;
        float4 v = *(const float4*)&Us[r*USTR + qq*4];
        *(float4*)(g_H + row0*SD + (size_t)f*4) = v;
    }
}

// ---------------- k2ab: superchunk prefixes + cross-superchunk scan (block/batch) ----------------
__global__ void __launch_bounds__(256) k2ab() {
    int tid = threadIdx.x;
    int b = blockIdx.x;
    int n = tid & 15;
    // phase 1: 16 half-warps, one per superchunk of this batch
    {
        int g = b*NSC + (tid >> 4);
        float Ar[16];
#pragma unroll
        for (int k = 0; k < 16; k++) Ar[k] = g_ALpow[256 + n*16 + k];   // AL
        float Pv = 0.f;
#pragma unroll
        for (int j = 0; j < NSUP; j++) {
            g_Pfx[(g*17 + j)*16 + n] = Pv;
            int c = g*NSUP + j;
            float s = g_H[((size_t)c*LCH + (LCH-1))*SD + n];
            float acc0 = s, acc1 = 0.f, acc2 = 0.f, acc3 = 0.f;
#pragma unroll
            for (int m = 0; m < 16; m += 4) {
                acc0 = fmaf(Ar[m],   __shfl_sync(FULLMASK, Pv, m,   16), acc0);
                acc1 = fmaf(Ar[m+1], __shfl_sync(FULLMASK, Pv, m+1, 16), acc1);
                acc2 = fmaf(Ar[m+2], __shfl_sync(FULLMASK, Pv, m+2, 16), acc2);
                acc3 = fmaf(Ar[m+3], __shfl_sync(FULLMASK, Pv, m+3, 16), acc3);
            }
            Pv = (acc0 + acc1) + (acc2 + acc3);
        }
        g_Pfx[(g*17 + 16)*16 + n] = Pv;
    }
    __syncthreads();
    // phase 2: half-warp 0 scans across superchunks with AL^16
    if (tid < 16) {
        float Ar[16];
#pragma unroll
        for (int k = 0; k < 16; k++) Ar[k] = g_ALpow[16*256 + n*16 + k];
        float H = 0.f;
#pragma unroll
        for (int s = 0; s < NSC; s++) {
            int g = b*NSC + s;
            g_Hsup[g*16 + n] = H;
            float P16 = g_Pfx[(g*17 + 16)*16 + n];
            float acc0 = P16, acc1 = 0.f, acc2 = 0.f, acc3 = 0.f;
#pragma unroll
            for (int m = 0; m < 16; m += 4) {
                acc0 = fmaf(Ar[m],   __shfl_sync(FULLMASK, H, m,   16), acc0);
                acc1 = fmaf(Ar[m+1], __shfl_sync(FULLMASK, H, m+1, 16), acc1);
                acc2 = fmaf(Ar[m+2], __shfl_sync(FULLMASK, H, m+2, 16), acc2);
                acc3 = fmaf(Ar[m+3], __shfl_sync(FULLMASK, H, m+3, 16), acc3);
            }
            H = (acc0 + acc1) + (acc2 + acc3);
        }
    }
}

// ---------------- K3f: Y = [X|H] @ [D|C]^T with in-kernel h reconstruction ----------------
// h = l + A^{j+1} hprev is rebuilt inside the tile: hprev from Pfx/Hsup, then
// 16 half-warp chains (4 chunks x 4 phases) w <- A^4 w add corrections into Zs.
#define WSTR 82
#define APAD 17
__global__ void __launch_bounds__(256) k3f(const float* __restrict__ x,
                                           const float* __restrict__ C,
                                           const float* __restrict__ D,
                                           float* __restrict__ y) {
    __shared__ __align__(16) float Zs[128*40];       // 20.5 KB
    __shared__ __align__(16) float Ws[64*WSTR];      // 21.0 KB
    __shared__ float sA4[4*16*APAD];                 // A^1..A^4, 4.35 KB
    __shared__ float hpv[4*16];                      // hprev per chunk
    int tid = threadIdx.x;
    size_t row0 = (size_t)blockIdx.x * 128;
    int tr = tid >> 4, tc = tid & 15;

    // W = [D|C]
#pragma unroll
    for (int i = 0; i < 8; i++) {
        int f = tid + 256*i;
        int o = f >> 5, k0 = (f & 31) << 1;
        float2 v = *(const float2*)(D + o*64 + k0);
        *(float2*)&Ws[o*WSTR + k0] = v;
    }
#pragma unroll
    for (int i = 0; i < 2; i++) {
        int f = tid + 256*i;
        int o = f >> 3, k0 = (f & 7) << 1;
        float2 v = *(const float2*)(C + o*16 + k0);
        *(float2*)&Ws[o*WSTR + 64 + k0] = v;
    }
    // A^1..A^4 into padded smem
#pragma unroll
    for (int i = 0; i < 4; i++) {
        int f = tid + 256*i;
        int jl = f >> 8, e = f & 255;
        sA4[jl*(16*APAD) + (e >> 4)*APAD + (e & 15)] = g_Apow[f];
    }
    // hprev for the block's 4 chunks: hprev = AL^{js} Hsup[gsup] + Pfx[gsup][js]
    if (tid < 64) {
        int cl = tid >> 4, n = tid & 15;
        int cg = blockIdx.x*4 + cl;
        int gsup = cg >> 4, js = cg & 15;
        float s = g_Pfx[((size_t)gsup*17 + js)*16 + n];
        const float* alr = g_ALpow + js*256 + n*16;
        const float* hs = g_Hsup + gsup*16;
#pragma unroll
        for (int k = 0; k < 16; k++) s = fmaf(alr[k], hs[k], s);
        hpv[cl*16 + n] = s;
    }

    unsigned long long acc[8][4];
#pragma unroll
    for (int m = 0; m < 8; m++)
#pragma unroll
        for (int c = 0; c < 4; c++) acc[m][c] = 0ull;

    const float* za = Zs + (tr*8)*40;

    // ---- phase 1: x k0..39 ----
#pragma unroll
    for (int i = 0; i < 5; i++) {
        int f = tid + 256*i;
        int r = f / 10, qq = f % 10;
        float4 v = *(const float4*)(x + (row0 + r)*64 + qq*4);
        *(float4*)&Zs[r*40 + qq*4] = v;
    }
    __syncthreads();
#pragma unroll
    for (int kp = 0; kp < 20; kp++) {
        unsigned long long a2[8], b2[4];
#pragma unroll
        for (int m = 0; m < 8; m++)
            a2[m] = *(const unsigned long long*)(za + m*40 + 2*kp);
#pragma unroll
        for (int c = 0; c < 4; c++)
            b2[c] = *(const unsigned long long*)(Ws + (tc + 16*c)*WSTR + 2*kp);
#pragma unroll
        for (int m = 0; m < 8; m++)
#pragma unroll
            for (int c = 0; c < 4; c++)
                asm("fma.rn.f32x2 %0, %1, %2, %0;"
                    : "+l"(acc[m][c]) : "l"(a2[m]), "l"(b2[c]));
    }
    __syncthreads();
    // ---- phase 2 staging: x k40..63 -> cols 0..23, l -> cols 24..39 ----
#pragma unroll
    for (int i = 0; i < 3; i++) {
        int f = tid + 256*i;
        if (f < 768) {
            int r = f / 6, qq = f % 6;
            float4 v = *(const float4*)(x + (row0 + r)*64 + 40 + qq*4);
            *(float4*)&Zs[r*40 + qq*4] = v;
        }
    }
#pragma unroll
    for (int i = 0; i < 2; i++) {
        int f = tid + 256*i;
        int r = f >> 2, qq = f & 3;
        float4 v = *(const float4*)(g_H + (row0 + r)*16 + qq*4);
        *(float4*)&Zs[r*40 + 24 + qq*4] = v;
    }
    __syncthreads();
    // ---- correction chains: w_j = A^{j+1} hprev, j = m + 4s ----
    {
        int hw = tid >> 4, cl = hw >> 2, mph = hw & 3, n = tid & 15;
        const float* Am = sA4 + mph*(16*APAD) + n*APAD;
        const float* hp = hpv + cl*16;
        float w = 0.f;
#pragma unroll
        for (int k = 0; k < 16; k++) w = fmaf(Am[k], hp[k], w);
        float A4r[16];
#pragma unroll
        for (int k = 0; k < 16; k++) A4r[k] = sA4[3*(16*APAD) + n*APAD + k];
#pragma unroll
        for (int s = 0; s < 8; s++) {
            int j = mph + 4*s;
            Zs[(cl*32 + j)*40 + 24 + n] += w;
            if (s < 7) {
                float a0 = 0.f, a1 = 0.f, a2 = 0.f, a3 = 0.f;
#pragma unroll
                for (int m = 0; m < 16; m += 4) {
                    a0 = fmaf(A4r[m],   __shfl_sync(FULLMASK, w, m,   16), a0);
                    a1 = fmaf(A4r[m+1], __shfl_sync(FULLMASK, w, m+1, 16), a1);
                    a2 = fmaf(A4r[m+2], __shfl_sync(FULLMASK, w, m+2, 16), a2);
                    a3 = fmaf(A4r[m+3], __shfl_sync(FULLMASK, w, m+3, 16), a3);
                }
                w = (a0 + a1) + (a2 + a3);
            }
        }
    }
    __syncthreads();
    // ---- phase 2 compute ----
#pragma unroll
    for (int kp = 0; kp < 20; kp++) {
        unsigned long long a2[8], b2[4];
#pragma unroll
        for (int m = 0; m < 8; m++)
            a2[m] = *(const unsigned long long*)(za + m*40 + 2*kp);
#pragma unroll
        for (int c = 0; c < 4; c++)
            b2[c] = *(const unsigned long long*)(Ws + (tc + 16*c)*WSTR + 40 + 2*kp);
#pragma unroll
        for (int m = 0; m < 8; m++)
#pragma unroll
            for (int c = 0; c < 4; c++)
                asm("fma.rn.f32x2 %0, %1, %2, %0;"
                    : "+l"(acc[m][c]) : "l"(a2[m]), "l"(b2[c]));
    }

#pragma unroll
    for (int m = 0; m < 8; m++) {
        size_t row = row0 + tr*8 + m;
#pragma unroll
        for (int c = 0; c < 4; c++) {
            float lo, hi;
            asm("mov.b64 {%0,%1}, %2;" : "=f"(lo), "=f"(hi) : "l"(acc[m][c]));
            y[row*64 + tc + 16*c] = lo + hi;
        }
    }
}

extern "C" void kernel_launch(void* const* d_in, const int* in_sizes, int n_in,
                              void* d_out, int out_size) {
    const float* x  = (const float*)d_in[0];
    const float* ll = (const float*)d_in[1];
    const float* p  = (const float*)d_in[2];
    const float* q  = (const float*)d_in[3];
    const float* B  = (const float*)d_in[4];
    const float* C  = (const float*)d_in[5];
    const float* D  = (const float*)d_in[6];
    const float* P  = (const float*)d_in[7];
    float* y = (float*)d_out;

    k0_setup<<<1, 256>>>(ll, p, q, B, P);
    kbxs<<<(NBATCH*SEQLEN)/128, 256>>>(x);
    k2ab<<<NBATCH, 256>>>();
    k3f<<<(NBATCH*SEQLEN)/128, 256>>>(x, C, D, y);   // profiled slot (4th)
}

// round 14
// speedup vs baseline: 1.0510x; 1.0510x over previous
#include <cuda_runtime.h>
#include <math.h>

#define SD     16
#define IDIM   64
#define ODIM   64
#define NBATCH 32
#define SEQLEN 8192
#define LCH    32
#define NCH    (SEQLEN/LCH)
#define NSUP   16
#define NSC    (NCH/NSUP)
#define DTVAL  1.0f
#define FULLMASK 0xffffffffu

__device__ __align__(16) float g_Ad[SD*SD];
__device__ __align__(16) float g_Bd[SD*IDIM];
__device__ __align__(16) float g_Apow[LCH*SD*SD];
__device__ __align__(16) float g_ALpow[17*SD*SD];
__device__ __align__(16) float g_H[NBATCH*SEQLEN*SD];
__device__ __align__(16) float g_Pfx[NBATCH*NSC*17*SD];
__device__ __align__(16) float g_Hsup[NBATCH*NSC*SD];

// ---------------- K0: discretization + power tables ----------------
__global__ void k0_setup(const float* __restrict__ ll, const float* __restrict__ p,
                         const float* __restrict__ q,  const float* __restrict__ B,
                         const float* __restrict__ P) {
    __shared__ float core[SD*SD], tmp[SD*SD], Ac[SD*SD];
    __shared__ float aug[SD][96];
    __shared__ float fvec[SD];
    __shared__ float prow[96];
    int t = threadIdx.x;

    if (t < SD*SD) {
        int i = t >> 4, j = t & 15;
        float v = p[i] * q[j];
        if (i == j) v -= expf(ll[i]);
        core[t] = v;
    }
    __syncthreads();
    if (t < SD*SD) {
        int i = t >> 4, j = t & 15;
        float s = 0.f;
        for (int k = 0; k < SD; k++) s += P[i*SD+k] * core[k*SD+j];
        tmp[t] = s;
    }
    __syncthreads();
    if (t < SD*SD) {
        int i = t >> 4, j = t & 15;
        float s = 0.f;
        for (int k = 0; k < SD; k++) s += tmp[i*SD+k] * P[j*SD+k];
        Ac[t] = s;
    }
    __syncthreads();
    for (int f = t; f < SD*96; f += 256) {
        int r = f / 96, c = f % 96;
        float v;
        if (c < 16)      v = (r == c      ? 1.f : 0.f) - 0.5f*DTVAL*Ac[r*SD+c];
        else if (c < 32) v = (r == (c-16) ? 1.f : 0.f) + 0.5f*DTVAL*Ac[r*SD+(c-16)];
        else             v = DTVAL * B[r*IDIM + (c-32)];
        aug[r][c] = v;
    }
    __syncthreads();
    for (int col = 0; col < SD; col++) {
        if (t < 96) prow[t] = aug[col][t];
        if (t < SD) fvec[t] = aug[t][col];
        __syncthreads();
        float ipv = 1.f / prow[col];
        for (int f = t; f < SD*96; f += 256) {
            int r = f / 96, c = f % 96;
            if (r == col) aug[r][c] = prow[c] * ipv;
            else          aug[r][c] = fmaf(-fvec[r]*ipv, prow[c], aug[r][c]);
        }
        __syncthreads();
    }
    if (t < SD*SD) { int r = t >> 4, c = t & 15; float v = aug[r][16+c]; g_Ad[t] = v; g_Apow[t] = v; }
    for (int f = t; f < SD*IDIM; f += 256) { int r = f / IDIM, c = f % IDIM; g_Bd[f] = aug[r][32+c]; }
    __syncthreads();
    for (int m = 1; m <= LCH/2; m <<= 1) {
        for (int f = t; f < m*256; f += 256) {
            int i = f >> 8, e = f & 255, r = e >> 4, c2 = e & 15;
            const float* L = g_Apow + i*256 + r*16;
            const float* R = g_Apow + (m-1)*256;
            float s = 0.f;
#pragma unroll
            for (int k = 0; k < 16; k++) s = fmaf(L[k], R[k*16 + c2], s);
            g_Apow[(m+i)*256 + e] = s;
        }
        __syncthreads();
    }
    if (t < 256) {
        int r = t >> 4, c = t & 15;
        g_ALpow[t] = (r == c) ? 1.f : 0.f;
        g_ALpow[256 + t] = g_Apow[(LCH-1)*256 + t];
    }
    __syncthreads();
    for (int m = 1; m <= 8; m <<= 1) {
        for (int f = t; f < m*256; f += 256) {
            int i = (f >> 8) + 1, e = f & 255, r = e >> 4, c2 = e & 15;
            const float* L = g_ALpow + i*256 + r*16;
            const float* R = g_ALpow + m*256;
            float s = 0.f;
#pragma unroll
            for (int k = 0; k < 16; k++) s = fmaf(L[k], R[k*16 + c2], s);
            g_ALpow[(m+i)*256 + e] = s;
        }
        __syncthreads();
    }
}

// ---------------- kBxS: u = x @ Bd^T + in-smem local scan ----------------
#define XSTR 66
#define USTR 20
__global__ void __launch_bounds__(256) kbxs(const float* __restrict__ x) {
    __shared__ __align__(16) float Xs[128*XSTR];
    __shared__ float Bs[16*66];
    __shared__ float As[16*17];
    int tid = threadIdx.x;
    size_t row0 = (size_t)blockIdx.x * 128;

    for (int i = tid; i < SD*IDIM; i += 256) {
        int nn = i >> 6, kk = i & 63;
        Bs[nn*66 + kk] = g_Bd[i];
    }
    if (tid < SD*SD) As[(tid >> 4)*17 + (tid & 15)] = g_Ad[tid];
#pragma unroll
    for (int i = 0; i < 16; i++) {
        int f = tid + 256*i;
        int r = f >> 5, qq = f & 31;
        float2 v = *(const float2*)(x + (row0 + r)*64 + qq*2);
        *(float2*)&Xs[r*XSTR + qq*2] = v;
    }
    __syncthreads();

    unsigned long long acc[4][4];
    int tr = tid >> 2, tc = tid & 3;
    if (tid < 128) {
#pragma unroll
        for (int m = 0; m < 4; m++)
#pragma unroll
            for (int c = 0; c < 4; c++) acc[m][c] = 0ull;
        const float* xa = Xs + (tr*4)*XSTR;
#pragma unroll
        for (int kp = 0; kp < 32; kp++) {
            unsigned long long a2[4], b2[4];
#pragma unroll
            for (int m = 0; m < 4; m++)
                a2[m] = *(const unsigned long long*)(xa + m*XSTR + 2*kp);
#pragma unroll
            for (int c = 0; c < 4; c++)
                b2[c] = *(const unsigned long long*)(Bs + (tc + 4*c)*66 + 2*kp);
#pragma unroll
            for (int m = 0; m < 4; m++)
#pragma unroll
                for (int c = 0; c < 4; c++)
                    asm("fma.rn.f32x2 %0, %1, %2, %0;"
                        : "+l"(acc[m][c]) : "l"(a2[m]), "l"(b2[c]));
        }
    }
    __syncthreads();
    float* Us = Xs;
    if (tid < 128) {
#pragma unroll
        for (int m = 0; m < 4; m++)
#pragma unroll
            for (int c = 0; c < 4; c++) {
                float lo, hi;
                asm("mov.b64 {%0,%1}, %2;" : "=f"(lo), "=f"(hi) : "l"(acc[m][c]));
                Us[(tr*4 + m)*USTR + tc + 4*c] = lo + hi;
            }
    }
    __syncthreads();

    if (tid < 64) {
        int hw = tid >> 4, n = tid & 15;
        float Ar[16];
#pragma unroll
        for (int k = 0; k < 16; k++) Ar[k] = As[n*17 + k];
        float* u = Us + hw*32*USTR + n;
        float h = 0.f;
        float uc = u[0];
#pragma unroll
        for (int i = 0; i < LCH; i++) {
            float un = (i < LCH-1) ? u[(i+1)*USTR] : 0.f;
            float acc0 = uc, acc1 = 0.f, acc2 = 0.f, acc3 = 0.f;
#pragma unroll
            for (int m = 0; m < 16; m += 4) {
                acc0 = fmaf(Ar[m],   __shfl_sync(FULLMASK, h, m,   16), acc0);
                acc1 = fmaf(Ar[m+1], __shfl_sync(FULLMASK, h, m+1, 16), acc1);
                acc2 = fmaf(Ar[m+2], __shfl_sync(FULLMASK, h, m+2, 16), acc2);
                acc3 = fmaf(Ar[m+3], __shfl_sync(FULLMASK, h, m+3, 16), acc3);
            }
            h = (acc0 + acc1) + (acc2 + acc3);
            u[i*USTR] = h;
            uc = un;
        }
    }
    __syncthreads();

#pragma unroll
    for (int i = 0; i < 2; i++) {
        int f = tid + 256*i;
        int r = f >> 2, qq = f & 3;
        float4 v = *(const float4*)&Us[r*USTR + qq*4];
        *(float4*)(g_H + row0*SD + (size_t)f*4) = v;
    }
}

// ---------------- k2ab: superchunk prefixes + cross-superchunk scan ----------------
__global__ void __launch_bounds__(256) k2ab() {
    int tid = threadIdx.x;
    int b = blockIdx.x;
    int n = tid & 15;
    {
        int g = b*NSC + (tid >> 4);
        float Ar[16];
#pragma unroll
        for (int k = 0; k < 16; k++) Ar[k] = g_ALpow[256 + n*16 + k];
        float Pv = 0.f;
#pragma unroll
        for (int j = 0; j < NSUP; j++) {
            g_Pfx[(g*17 + j)*16 + n] = Pv;
            int c = g*NSUP + j;
            float s = g_H[((size_t)c*LCH + (LCH-1))*SD + n];
            float acc0 = s, acc1 = 0.f, acc2 = 0.f, acc3 = 0.f;
#pragma unroll
            for (int m = 0; m < 16; m += 4) {
                acc0 = fmaf(Ar[m],   __shfl_sync(FULLMASK, Pv, m,   16), acc0);
                acc1 = fmaf(Ar[m+1], __shfl_sync(FULLMASK, Pv, m+1, 16), acc1);
                acc2 = fmaf(Ar[m+2], __shfl_sync(FULLMASK, Pv, m+2, 16), acc2);
                acc3 = fmaf(Ar[m+3], __shfl_sync(FULLMASK, Pv, m+3, 16), acc3);
            }
            Pv = (acc0 + acc1) + (acc2 + acc3);
        }
        g_Pfx[(g*17 + 16)*16 + n] = Pv;
    }
    __syncthreads();
    if (tid < 16) {
        float Ar[16];
#pragma unroll
        for (int k = 0; k < 16; k++) Ar[k] = g_ALpow[16*256 + n*16 + k];
        float H = 0.f;
#pragma unroll
        for (int s = 0; s < NSC; s++) {
            int g = b*NSC + s;
            g_Hsup[g*16 + n] = H;
            float P16 = g_Pfx[(g*17 + 16)*16 + n];
            float acc0 = P16, acc1 = 0.f, acc2 = 0.f, acc3 = 0.f;
#pragma unroll
            for (int m = 0; m < 16; m += 4) {
                acc0 = fmaf(Ar[m],   __shfl_sync(FULLMASK, H, m,   16), acc0);
                acc1 = fmaf(Ar[m+1], __shfl_sync(FULLMASK, H, m+1, 16), acc1);
                acc2 = fmaf(Ar[m+2], __shfl_sync(FULLMASK, H, m+2, 16), acc2);
                acc3 = fmaf(Ar[m+3], __shfl_sync(FULLMASK, H, m+3, 16), acc3);
            }
            H = (acc0 + acc1) + (acc2 + acc3);
        }
    }
}

// ---------------- K3g: Y = [X|H] @ [D|C]^T, 512 threads, 4x4 tile ----------------
#define WSTR 82
#define APAD 17
__global__ void __launch_bounds__(512, 1) k3g(const float* __restrict__ x,
                                              const float* __restrict__ C,
                                              const float* __restrict__ D,
                                              float* __restrict__ y) {
    __shared__ __align__(16) float Zs[128*40];
    __shared__ __align__(16) float Ws[64*WSTR];
    __shared__ float sA4[4*16*APAD];
    __shared__ float hpv[4*16];
    int tid = threadIdx.x;
    size_t row0 = (size_t)blockIdx.x * 128;
    int tr = tid >> 4, tc = tid & 15;    // 32 row-groups x 16 col-groups

    // W = [D|C]
#pragma unroll
    for (int i = 0; i < 4; i++) {
        int f = tid + 512*i;                    // 2048 float2 = D
        int o = f >> 5, k0 = (f & 31) << 1;
        float2 v = *(const float2*)(D + o*64 + k0);
        *(float2*)&Ws[o*WSTR + k0] = v;
    }
    {
        int f = tid;                            // 512 float2 = C
        int o = f >> 3, k0 = (f & 7) << 1;
        float2 v = *(const float2*)(C + o*16 + k0);
        *(float2*)&Ws[o*WSTR + 64 + k0] = v;
    }
    // A^1..A^4
#pragma unroll
    for (int i = 0; i < 2; i++) {
        int f = tid + 512*i;
        int jl = f >> 8, e = f & 255;
        sA4[jl*(16*APAD) + (e >> 4)*APAD + (e & 15)] = g_Apow[f];
    }
    // hprev per chunk
    if (tid < 64) {
        int cl = tid >> 4, n = tid & 15;
        int cg = blockIdx.x*4 + cl;
        int gsup = cg >> 4, js = cg & 15;
        float s = g_Pfx[((size_t)gsup*17 + js)*16 + n];
        const float* alr = g_ALpow + js*256 + n*16;
        const float* hs = g_Hsup + gsup*16;
#pragma unroll
        for (int k = 0; k < 16; k++) s = fmaf(alr[k], hs[k], s);
        hpv[cl*16 + n] = s;
    }

    unsigned long long acc[4][4];
#pragma unroll
    for (int m = 0; m < 4; m++)
#pragma unroll
        for (int c = 0; c < 4; c++) acc[m][c] = 0ull;

    const float* za = Zs + (tr*4)*40;

    // ---- phase 1: x k0..39 ----
#pragma unroll
    for (int i = 0; i < 3; i++) {
        int f = tid + 512*i;
        if (f < 1280) {
            int r = f / 10, qq = f % 10;
            float4 v = *(const float4*)(x + (row0 + r)*64 + qq*4);
            *(float4*)&Zs[r*40 + qq*4] = v;
        }
    }
    __syncthreads();
#pragma unroll
    for (int kp = 0; kp < 20; kp++) {
        unsigned long long a2[4], b2[4];
#pragma unroll
        for (int m = 0; m < 4; m++)
            a2[m] = *(const unsigned long long*)(za + m*40 + 2*kp);
#pragma unroll
        for (int c = 0; c < 4; c++)
            b2[c] = *(const unsigned long long*)(Ws + (tc + 16*c)*WSTR + 2*kp);
#pragma unroll
        for (int m = 0; m < 4; m++)
#pragma unroll
            for (int c = 0; c < 4; c++)
                asm("fma.rn.f32x2 %0, %1, %2, %0;"
                    : "+l"(acc[m][c]) : "l"(a2[m]), "l"(b2[c]));
    }
    __syncthreads();
    // ---- phase 2 staging ----
#pragma unroll
    for (int i = 0; i < 2; i++) {
        int f = tid + 512*i;
        if (f < 768) {
            int r = f / 6, qq = f % 6;
            float4 v = *(const float4*)(x + (row0 + r)*64 + 40 + qq*4);
            *(float4*)&Zs[r*40 + qq*4] = v;
        }
    }
    {
        int f = tid;                            // 512 float4: l values
        int r = f >> 2, qq = f & 3;
        float4 v = *(const float4*)(g_H + (row0 + r)*16 + qq*4);
        *(float4*)&Zs[r*40 + 24 + qq*4] = v;
    }
    __syncthreads();
    // ---- correction chains (16 half-warps in tid<256) ----
    if (tid < 256) {
        int hw = tid >> 4, cl = hw >> 2, mph = hw & 3, n = tid & 15;
        const float* Am = sA4 + mph*(16*APAD) + n*APAD;
        const float* hp = hpv + cl*16;
        float w = 0.f;
#pragma unroll
        for (int k = 0; k < 16; k++) w = fmaf(Am[k], hp[k], w);
        float A4r[16];
#pragma unroll
        for (int k = 0; k < 16; k++) A4r[k] = sA4[3*(16*APAD) + n*APAD + k];
#pragma unroll
        for (int s = 0; s < 8; s++) {
            int j = mph + 4*s;
            Zs[(cl*32 + j)*40 + 24 + n] += w;
            if (s < 7) {
                float a0 = 0.f, a1 = 0.f, a2 = 0.f, a3 = 0.f;
#pragma unroll
                for (int m = 0; m < 16; m += 4) {
                    a0 = fmaf(A4r[m],   __shfl_sync(FULLMASK, w, m,   16), a0);
                    a1 = fmaf(A4r[m+1], __shfl_sync(FULLMASK, w, m+1, 16), a1);
                    a2 = fmaf(A4r[m+2], __shfl_sync(FULLMASK, w, m+2, 16), a2);
                    a3 = fmaf(A4r[m+3], __shfl_sync(FULLMASK, w, m+3, 16), a3);
                }
                w = (a0 + a1) + (a2 + a3);
            }
        }
    }
    __syncthreads();
    // ---- phase 2 compute ----
#pragma unroll
    for (int kp = 0; kp < 20; kp++) {
        unsigned long long a2[4], b2[4];
#pragma unroll
        for (int m = 0; m < 4; m++)
            a2[m] = *(const unsigned long long*)(za + m*40 + 2*kp);
#pragma unroll
        for (int c = 0; c < 4; c++)
            b2[c] = *(const unsigned long long*)(Ws + (tc + 16*c)*WSTR + 40 + 2*kp);
#pragma unroll
        for (int m = 0; m < 4; m++)
#pragma unroll
            for (int c = 0; c < 4; c++)
                asm("fma.rn.f32x2 %0, %1, %2, %0;"
                    : "+l"(acc[m][c]) : "l"(a2[m]), "l"(b2[c]));
    }

#pragma unroll
    for (int m = 0; m < 4; m++) {
        size_t row = row0 + tr*4 + m;
#pragma unroll
        for (int c = 0; c < 4; c++) {
            float lo, hi;
            asm("mov.b64 {%0,%1}, %2;" : "=f"(lo), "=f"(hi) : "l"(acc[m][c]));
            y[row*64 + tc + 16*c] = lo + hi;
        }
    }
}

extern "C" void kernel_launch(void* const* d_in, const int* in_sizes, int n_in,
                              void* d_out, int out_size) {
    const float* x  = (const float*)d_in[0];
    const float* ll = (const float*)d_in[1];
    const float* p  = (const float*)d_in[2];
    const float* q  = (const float*)d_in[3];
    const float* B  = (const float*)d_in[4];
    const float* C  = (const float*)d_in[5];
    const float* D  = (const float*)d_in[6];
    const float* P  = (const float*)d_in[7];
    float* y = (float*)d_out;

    k0_setup<<<1, 256>>>(ll, p, q, B, P);
    kbxs<<<(NBATCH*SEQLEN)/128, 256>>>(x);
    k2ab<<<NBATCH, 256>>>();
    k3g<<<(NBATCH*SEQLEN)/128, 512>>>(x, C, D, y);   // profiled slot (4th)
}